// round 5
// baseline (speedup 1.0000x reference)
#include <cuda_runtime.h>
#include <cuda_bf16.h>

#define NN 50000
#define NE 800000
#define DD 64
#define NN16 (NN * 16)
#define NE16 (NE * 16)

// Scratch (static device globals — no allocation allowed). float4 => 16B aligned.
__device__ float4 g_g[NN * 16];    // g = (x@W) * dinv[row]
__device__ float4 g_acc[NN * 16];  // scatter accumulator / hidden activation
__device__ float  g_dinv[NN];      // deg -> rsqrt(deg)
__device__ int    g_src[NE];       // converted edge sources (int32)
__device__ int    g_dst[NE];       // converted edge targets (int32)
__device__ int    g_is64;          // 1 if edge buffer is int64, 0 if int32

// ---------------- edge dtype detection + conversion ----------------
// The harness may deliver edge_index as int32 or int64. Detect by sampling:
// if 64 consecutive int64 interpretations are all in [0, NN) it's int64
// (packed int32 would need 64 odd-words == 0, probability ~0).
__global__ void k_detect(const void* __restrict__ ei) {
    const long long* p = (const long long*)ei;
    int ok = 1;
    for (int i = 0; i < 64; i++) {
        long long v = p[i];
        if (v < 0 || v >= NN) { ok = 0; break; }
    }
    g_is64 = ok;
}

__global__ __launch_bounds__(256) void k_convert(const void* __restrict__ ei) {
    int e = blockIdx.x * blockDim.x + threadIdx.x;
    if (e >= NE) return;
    int s, d;
    if (g_is64) {
        const long long* p = (const long long*)ei;
        s = (int)p[e];
        d = (int)p[NE + e];
    } else {
        const int* p = (const int*)ei;
        s = p[e];
        d = p[NE + e];
    }
    // clamp: protects against a wrong detection wedging the GPU
    s = min(max(s, 0), NN - 1);
    d = min(max(d, 0), NN - 1);
    g_src[e] = s;
    g_dst[e] = d;
}

// ---------------- degree / norm ----------------

__global__ void k_init_deg() {
    int i = blockIdx.x * blockDim.x + threadIdx.x;
    if (i < NN) g_dinv[i] = 1.0f;  // self-loop contributes 1
}

__global__ void k_count_deg() {
    int e = blockIdx.x * blockDim.x + threadIdx.x;
    if (e < NE) atomicAdd(&g_dinv[g_dst[e]], 1.0f);
}

__global__ void k_rsqrt_deg() {
    int i = blockIdx.x * blockDim.x + threadIdx.x;
    if (i < NN) g_dinv[i] = rsqrtf(g_dinv[i]);  // deg >= 1 always
}

// ---------------- GEMM + scale epilogue ----------------
// h = X @ W ;  g = h * dinv[row] ; acc = g  (self-loop pre-seeded, no memset)
// use_hidden: X = g_acc (hidden, in-place safe: block reads rows [base,base+64)
// into smem before writing those same rows).
__global__ __launch_bounds__(256) void k_gemm_scale(const float* __restrict__ Xext,
                                                    const float* __restrict__ W,
                                                    int use_hidden) {
    __shared__ float sW[DD * DD];   // [k][n]
    __shared__ float sX[64 * DD];   // [r][k]
    const float* X = use_hidden ? (const float*)g_acc : Xext;

    int tid = threadIdx.x;
    int base = blockIdx.x * 64;

    float4* sW4 = (float4*)sW;
    const float4* W4 = (const float4*)W;
#pragma unroll
    for (int i = tid; i < DD * DD / 4; i += 256) sW4[i] = W4[i];

    float4* sX4 = (float4*)sX;
    const float4* X4 = (const float4*)X;
#pragma unroll
    for (int i = tid; i < 64 * DD / 4; i += 256) {
        int r = base + i / (DD / 4);
        sX4[i] = (r < NN) ? X4[(size_t)base * (DD / 4) + i]
                          : make_float4(0.f, 0.f, 0.f, 0.f);
    }
    __syncthreads();

    int c4 = tid & 15;          // which float4 of the output row
    int r0 = (tid >> 4) * 4;    // local row base (0..60)

    float4 acc0 = make_float4(0, 0, 0, 0), acc1 = acc0, acc2 = acc0, acc3 = acc0;
#pragma unroll
    for (int k = 0; k < DD; k++) {
        float4 w = sW4[k * 16 + c4];
        float x0 = sX[(r0 + 0) * DD + k];
        float x1 = sX[(r0 + 1) * DD + k];
        float x2 = sX[(r0 + 2) * DD + k];
        float x3 = sX[(r0 + 3) * DD + k];
        acc0.x += x0 * w.x; acc0.y += x0 * w.y; acc0.z += x0 * w.z; acc0.w += x0 * w.w;
        acc1.x += x1 * w.x; acc1.y += x1 * w.y; acc1.z += x1 * w.z; acc1.w += x1 * w.w;
        acc2.x += x2 * w.x; acc2.y += x2 * w.y; acc2.z += x2 * w.z; acc2.w += x2 * w.w;
        acc3.x += x3 * w.x; acc3.y += x3 * w.y; acc3.z += x3 * w.z; acc3.w += x3 * w.w;
    }

    float4 accs[4] = {acc0, acc1, acc2, acc3};
#pragma unroll
    for (int j = 0; j < 4; j++) {
        int r = base + r0 + j;
        if (r < NN) {
            float s = g_dinv[r];
            float4 v = make_float4(accs[j].x * s, accs[j].y * s,
                                   accs[j].z * s, accs[j].w * s);
            g_g[r * 16 + c4]   = v;
            g_acc[r * 16 + c4] = v;
        }
    }
}

// ---------------- edge scatter ----------------
// 16 threads per edge; each owns one float4 lane of the 64-dim row.
__global__ __launch_bounds__(256) void k_scatter() {
    int gid = blockIdx.x * blockDim.x + threadIdx.x;
    if (gid >= NE16) return;
    int e = gid >> 4;
    int s = gid & 15;
    int r = __ldg(&g_src[e]);
    int c = __ldg(&g_dst[e]);
    float4 v = g_g[r * 16 + s];
    float* a = (float*)&g_acc[c * 16 + s];
    atomicAdd(a + 0, v.x);
    atomicAdd(a + 1, v.y);
    atomicAdd(a + 2, v.z);
    atomicAdd(a + 3, v.w);
}

// ---------------- finalize ----------------
// out[i] = dinv[i]*acc[i] + b ; optional relu ; hidden stays in-place in g_acc
__global__ __launch_bounds__(256) void k_finalize(const float* __restrict__ bias,
                                                  float* __restrict__ outext,
                                                  int to_hidden_relu) {
    int gid = blockIdx.x * blockDim.x + threadIdx.x;
    if (gid >= NN16) return;
    int i = gid >> 4;
    int s = gid & 15;
    float4 a = g_acc[gid];
    float sc = g_dinv[i];
    float4 b = ((const float4*)bias)[s];
    float4 o = make_float4(a.x * sc + b.x, a.y * sc + b.y,
                           a.z * sc + b.z, a.w * sc + b.w);
    if (to_hidden_relu) {
        o.x = fmaxf(o.x, 0.f); o.y = fmaxf(o.y, 0.f);
        o.z = fmaxf(o.z, 0.f); o.w = fmaxf(o.w, 0.f);
        g_acc[gid] = o;
    } else {
        ((float4*)outext)[gid] = o;
    }
}

extern "C" void kernel_launch(void* const* d_in, const int* in_sizes, int n_in,
                              void* d_out, int out_size) {
    const float* x  = (const float*)d_in[0];
    const void*  ei = d_in[1];                  // [2, NE] int32 OR int64
    const float* W1 = (const float*)d_in[2];
    const float* b1 = (const float*)d_in[3];
    const float* W2 = (const float*)d_in[4];
    const float* b2 = (const float*)d_in[5];
    float* out = (float*)d_out;

    // dtype-detect + convert edge index to int32
    k_detect<<<1, 1>>>(ei);
    k_convert<<<(NE + 255) / 256, 256>>>(ei);

    // degree / dinv (same for both layers)
    k_init_deg<<<(NN + 255) / 256, 256>>>();
    k_count_deg<<<(NE + 255) / 256, 256>>>();
    k_rsqrt_deg<<<(NN + 255) / 256, 256>>>();

    // Layer 1
    k_gemm_scale<<<(NN + 63) / 64, 256>>>(x, W1, 0);
    k_scatter<<<(NE16 + 255) / 256, 256>>>();
    k_finalize<<<(NN16 + 255) / 256, 256>>>(b1, nullptr, 1);

    // Layer 2 (reads hidden in-place from g_acc)
    k_gemm_scale<<<(NN + 63) / 64, 256>>>(nullptr, W2, 1);
    k_scatter<<<(NE16 + 255) / 256, 256>>>();
    k_finalize<<<(NN16 + 255) / 256, 256>>>(b2, out, 0);
}

// round 6
// speedup vs baseline: 2.1275x; 2.1275x over previous
#include <cuda_runtime.h>
#include <cuda_bf16.h>

#define NN 50000
#define NE 800000
#define DD 64
#define NN16 (NN * 16)

// Scratch (static device globals). float4 => 16B aligned.
__device__ float4 g_g[NN * 16];    // g = (X@W) * dinv[row]
__device__ float4 g_hid[NN * 16];  // hidden activation between layers
__device__ float  g_dinv[NN];      // rsqrt(deg+1)
__device__ int    g_src[NE];       // edge sources (int32)
__device__ int    g_dst[NE];       // edge targets (int32)
__device__ int    g_deg[NN];       // in-degree (excl. self loop)
__device__ int    g_off[NN + 1];   // CSR offsets
__device__ int    g_pos[NN];       // fill cursors
__device__ int    g_csr_src[NE];   // sources grouped by dst
__device__ int    g_is64;          // edge dtype flag

// ---------------- edge dtype detection ----------------
__global__ void k_detect(const void* __restrict__ ei) {
    const long long* p = (const long long*)ei;
    int ok = 1;
    for (int i = 0; i < 64; i++) {
        long long v = p[i];
        if (v < 0 || v >= NN) { ok = 0; break; }
    }
    g_is64 = ok;
}

__global__ void k_zero_deg() {
    int i = blockIdx.x * blockDim.x + threadIdx.x;
    if (i < NN) g_deg[i] = 0;
}

// convert to int32 + count in-degrees
__global__ __launch_bounds__(256) void k_convert_count(const void* __restrict__ ei) {
    int e = blockIdx.x * blockDim.x + threadIdx.x;
    if (e >= NE) return;
    int s, d;
    if (g_is64) {
        const long long* p = (const long long*)ei;
        s = (int)p[e];
        d = (int)p[NE + e];
    } else {
        const int* p = (const int*)ei;
        s = p[e];
        d = p[NE + e];
    }
    s = min(max(s, 0), NN - 1);
    d = min(max(d, 0), NN - 1);
    g_src[e] = s;
    g_dst[e] = d;
    atomicAdd(&g_deg[d], 1);
}

// single-block exclusive scan over g_deg -> g_off ; also pos=off, dinv
__global__ __launch_bounds__(1024) void k_scan() {
    __shared__ int part[1024];
    int tid = threadIdx.x;
    const int chunk = (NN + 1023) / 1024;
    int start = tid * chunk;
    int fin = min(start + chunk, NN);
    int s = 0;
    for (int i = start; i < fin; i++) s += g_deg[i];
    part[tid] = s;
    __syncthreads();
    // Hillis-Steele inclusive scan
    for (int d = 1; d < 1024; d <<= 1) {
        int v = (tid >= d) ? part[tid - d] : 0;
        __syncthreads();
        part[tid] += v;
        __syncthreads();
    }
    int run = (tid == 0) ? 0 : part[tid - 1];
    for (int i = start; i < fin; i++) {
        g_off[i] = run;
        g_pos[i] = run;
        g_dinv[i] = rsqrtf((float)(g_deg[i] + 1));  // +1 self loop
        run += g_deg[i];
    }
    if (tid == 1023) g_off[NN] = run;
}

__global__ __launch_bounds__(256) void k_fill() {
    int e = blockIdx.x * blockDim.x + threadIdx.x;
    if (e >= NE) return;
    int d = g_dst[e];
    int p = atomicAdd(&g_pos[d], 1);
    g_csr_src[p] = g_src[e];
}

// ---------------- GEMM + scale epilogue ----------------
// g = (X @ W) * dinv[row]
__global__ __launch_bounds__(256) void k_gemm_scale(const float* __restrict__ Xext,
                                                    const float* __restrict__ W,
                                                    int use_hidden) {
    __shared__ float sW[DD * DD];   // [k][n]
    __shared__ float sX[64 * DD];   // [r][k]
    const float* X = use_hidden ? (const float*)g_hid : Xext;

    int tid = threadIdx.x;
    int base = blockIdx.x * 64;

    float4* sW4 = (float4*)sW;
    const float4* W4 = (const float4*)W;
#pragma unroll
    for (int i = tid; i < DD * DD / 4; i += 256) sW4[i] = W4[i];

    float4* sX4 = (float4*)sX;
    const float4* X4 = (const float4*)X;
#pragma unroll
    for (int i = tid; i < 64 * DD / 4; i += 256) {
        int r = base + i / (DD / 4);
        sX4[i] = (r < NN) ? X4[(size_t)base * (DD / 4) + i]
                          : make_float4(0.f, 0.f, 0.f, 0.f);
    }
    __syncthreads();

    int c4 = tid & 15;
    int r0 = (tid >> 4) * 4;

    float4 acc0 = make_float4(0, 0, 0, 0), acc1 = acc0, acc2 = acc0, acc3 = acc0;
#pragma unroll
    for (int k = 0; k < DD; k++) {
        float4 w = sW4[k * 16 + c4];
        float x0 = sX[(r0 + 0) * DD + k];
        float x1 = sX[(r0 + 1) * DD + k];
        float x2 = sX[(r0 + 2) * DD + k];
        float x3 = sX[(r0 + 3) * DD + k];
        acc0.x += x0 * w.x; acc0.y += x0 * w.y; acc0.z += x0 * w.z; acc0.w += x0 * w.w;
        acc1.x += x1 * w.x; acc1.y += x1 * w.y; acc1.z += x1 * w.z; acc1.w += x1 * w.w;
        acc2.x += x2 * w.x; acc2.y += x2 * w.y; acc2.z += x2 * w.z; acc2.w += x2 * w.w;
        acc3.x += x3 * w.x; acc3.y += x3 * w.y; acc3.z += x3 * w.z; acc3.w += x3 * w.w;
    }

    float4 accs[4] = {acc0, acc1, acc2, acc3};
#pragma unroll
    for (int j = 0; j < 4; j++) {
        int r = base + r0 + j;
        if (r < NN) {
            float s = g_dinv[r];
            g_g[r * 16 + c4] = make_float4(accs[j].x * s, accs[j].y * s,
                                           accs[j].z * s, accs[j].w * s);
        }
    }
}

// ---------------- CSR gather-aggregate (+ finalize fused) ----------------
// 16 threads per node; thread s owns float4 lane s of the 64-dim row.
// out[i] = dinv[i]*(sum_{j in N(i)} g[j] + g[i]) + b ; optional relu.
__global__ __launch_bounds__(256) void k_aggregate(const float* __restrict__ bias,
                                                   float* __restrict__ outext,
                                                   int to_hidden_relu) {
    int gid = blockIdx.x * blockDim.x + threadIdx.x;
    if (gid >= NN16) return;
    int node = gid >> 4;
    int s = gid & 15;

    int beg = __ldg(&g_off[node]);
    int end = __ldg(&g_off[node + 1]);

    float4 a = g_g[node * 16 + s];  // self loop
    float ax = a.x, ay = a.y, az = a.z, aw = a.w;

    int e = beg;
    // unrolled-by-2 with src prefetch for MLP
    for (; e + 1 < end; e += 2) {
        int s0 = __ldg(&g_csr_src[e]);
        int s1 = __ldg(&g_csr_src[e + 1]);
        float4 v0 = g_g[s0 * 16 + s];
        float4 v1 = g_g[s1 * 16 + s];
        ax += v0.x + v1.x;
        ay += v0.y + v1.y;
        az += v0.z + v1.z;
        aw += v0.w + v1.w;
    }
    if (e < end) {
        int s0 = __ldg(&g_csr_src[e]);
        float4 v0 = g_g[s0 * 16 + s];
        ax += v0.x; ay += v0.y; az += v0.z; aw += v0.w;
    }

    float sc = g_dinv[node];
    float4 b = ((const float4*)bias)[s];
    float4 o = make_float4(ax * sc + b.x, ay * sc + b.y,
                           az * sc + b.z, aw * sc + b.w);
    if (to_hidden_relu) {
        o.x = fmaxf(o.x, 0.f); o.y = fmaxf(o.y, 0.f);
        o.z = fmaxf(o.z, 0.f); o.w = fmaxf(o.w, 0.f);
        g_hid[gid] = o;
    } else {
        ((float4*)outext)[gid] = o;
    }
}

extern "C" void kernel_launch(void* const* d_in, const int* in_sizes, int n_in,
                              void* d_out, int out_size) {
    const float* x  = (const float*)d_in[0];
    const void*  ei = d_in[1];                  // [2, NE] int32 OR int64
    const float* W1 = (const float*)d_in[2];
    const float* b1 = (const float*)d_in[3];
    const float* W2 = (const float*)d_in[4];
    const float* b2 = (const float*)d_in[5];
    float* out = (float*)d_out;

    // CSR build (once, used by both layers)
    k_detect<<<1, 1>>>(ei);
    k_zero_deg<<<(NN + 255) / 256, 256>>>();
    k_convert_count<<<(NE + 255) / 256, 256>>>(ei);
    k_scan<<<1, 1024>>>();
    k_fill<<<(NE + 255) / 256, 256>>>();

    // Layer 1
    k_gemm_scale<<<(NN + 63) / 64, 256>>>(x, W1, 0);
    k_aggregate<<<(NN16 + 255) / 256, 256>>>(b1, nullptr, 1);

    // Layer 2
    k_gemm_scale<<<(NN + 63) / 64, 256>>>(nullptr, W2, 1);
    k_aggregate<<<(NN16 + 255) / 256, 256>>>(b2, out, 0);
}

// round 7
// speedup vs baseline: 4.4246x; 2.0797x over previous
#include <cuda_runtime.h>
#include <cuda_bf16.h>

#define NN 50000
#define NE 800000
#define DD 64
#define NN16 (NN * 16)
#define SCAN_B 256
#define NBLK ((NN + SCAN_B - 1) / SCAN_B)   // 196

// Scratch (static device globals). float4 => 16B aligned.
__device__ float4 g_g[NN * 16];    // g = (X@W) * dinv[row]
__device__ float4 g_hid[NN * 16];  // hidden activation between layers
__device__ float  g_dinv[NN];      // rsqrt(deg+1)
__device__ int    g_src[NE];       // edge sources (int32)
__device__ int    g_dst[NE];       // edge targets (int32)
__device__ int    g_deg[NN];       // in-degree (excl. self loop)
__device__ int    g_off[NN + 1];   // CSR offsets
__device__ int    g_pos[NN];       // fill cursors
__device__ int    g_csr_src[NE];   // sources grouped by dst
__device__ int    g_part[NBLK];    // per-block degree sums
__device__ int    g_partoff[NBLK]; // exclusive block offsets
__device__ int    g_is64;          // edge dtype flag

// ---------------- edge dtype detection (1 warp, parallel) ----------------
__global__ void k_detect(const void* __restrict__ ei) {
    const long long* p = (const long long*)ei;
    int t = threadIdx.x;           // 64 threads
    long long v = p[t];
    int bad = (v < 0 || v >= NN) ? 1 : 0;
    __shared__ int anybad;
    if (t == 0) anybad = 0;
    __syncthreads();
    if (bad) atomicOr(&anybad, 1);
    __syncthreads();
    if (t == 0) g_is64 = !anybad;
}

__global__ void k_zero_deg() {
    int i = blockIdx.x * blockDim.x + threadIdx.x;
    if (i < NN) g_deg[i] = 0;
}

// convert to int32 + count in-degrees
__global__ __launch_bounds__(256) void k_convert_count(const void* __restrict__ ei) {
    int e = blockIdx.x * blockDim.x + threadIdx.x;
    if (e >= NE) return;
    int s, d;
    if (g_is64) {
        const long long* p = (const long long*)ei;
        s = (int)p[e];
        d = (int)p[NE + e];
    } else {
        const int* p = (const int*)ei;
        s = p[e];
        d = p[NE + e];
    }
    s = min(max(s, 0), NN - 1);
    d = min(max(d, 0), NN - 1);
    g_src[e] = s;
    g_dst[e] = d;
    atomicAdd(&g_deg[d], 1);
}

// ---------------- parallel 3-phase scan ----------------
// phase 1: per-block sum of degrees
__global__ __launch_bounds__(SCAN_B) void k_scan1() {
    __shared__ int sh[SCAN_B];
    int i = blockIdx.x * SCAN_B + threadIdx.x;
    int d = (i < NN) ? g_deg[i] : 0;
    // warp reduce then shared
    for (int o = 16; o > 0; o >>= 1) d += __shfl_down_sync(0xffffffffu, d, o);
    if ((threadIdx.x & 31) == 0) sh[threadIdx.x >> 5] = d;
    __syncthreads();
    if (threadIdx.x < 8) {
        int v = sh[threadIdx.x];
        for (int o = 4; o > 0; o >>= 1) v += __shfl_down_sync(0xffu, v, o);
        if (threadIdx.x == 0) g_part[blockIdx.x] = v;
    }
}

// phase 2: single block scans NBLK partials -> exclusive offsets
__global__ __launch_bounds__(256) void k_scan2() {
    __shared__ int sh[256];
    int t = threadIdx.x;
    int v = (t < NBLK) ? g_part[t] : 0;
    sh[t] = v;
    __syncthreads();
    for (int d = 1; d < 256; d <<= 1) {
        int u = (t >= d) ? sh[t - d] : 0;
        __syncthreads();
        sh[t] += u;
        __syncthreads();
    }
    if (t < NBLK) g_partoff[t] = sh[t] - v;  // exclusive
    if (t == 0) g_off[NN] = NE;              // total is known
}

// phase 3: block-local rescan, write off/pos/dinv
__global__ __launch_bounds__(SCAN_B) void k_scan3() {
    __shared__ int sh[SCAN_B];
    int i = blockIdx.x * SCAN_B + threadIdx.x;
    int t = threadIdx.x;
    int d = (i < NN) ? g_deg[i] : 0;
    sh[t] = d;
    __syncthreads();
    for (int o = 1; o < SCAN_B; o <<= 1) {
        int u = (t >= o) ? sh[t - o] : 0;
        __syncthreads();
        sh[t] += u;
        __syncthreads();
    }
    if (i < NN) {
        int off = g_partoff[blockIdx.x] + sh[t] - d;  // exclusive
        g_off[i] = off;
        g_pos[i] = off;
        g_dinv[i] = rsqrtf((float)(d + 1));  // +1 self loop
    }
}

__global__ __launch_bounds__(256) void k_fill() {
    int e = blockIdx.x * blockDim.x + threadIdx.x;
    if (e >= NE) return;
    int d = g_dst[e];
    int p = atomicAdd(&g_pos[d], 1);
    g_csr_src[p] = g_src[e];
}

// ---------------- GEMM + scale epilogue ----------------
// g = (X @ W) * dinv[row]
__global__ __launch_bounds__(256) void k_gemm_scale(const float* __restrict__ Xext,
                                                    const float* __restrict__ W,
                                                    int use_hidden) {
    __shared__ float sW[DD * DD];   // [k][n]
    __shared__ float sX[64 * DD];   // [r][k]
    const float* X = use_hidden ? (const float*)g_hid : Xext;

    int tid = threadIdx.x;
    int base = blockIdx.x * 64;

    float4* sW4 = (float4*)sW;
    const float4* W4 = (const float4*)W;
#pragma unroll
    for (int i = tid; i < DD * DD / 4; i += 256) sW4[i] = W4[i];

    float4* sX4 = (float4*)sX;
    const float4* X4 = (const float4*)X;
#pragma unroll
    for (int i = tid; i < 64 * DD / 4; i += 256) {
        int r = base + i / (DD / 4);
        sX4[i] = (r < NN) ? X4[(size_t)base * (DD / 4) + i]
                          : make_float4(0.f, 0.f, 0.f, 0.f);
    }
    __syncthreads();

    int c4 = tid & 15;
    int r0 = (tid >> 4) * 4;

    float4 acc0 = make_float4(0, 0, 0, 0), acc1 = acc0, acc2 = acc0, acc3 = acc0;
#pragma unroll
    for (int k = 0; k < DD; k++) {
        float4 w = sW4[k * 16 + c4];
        float x0 = sX[(r0 + 0) * DD + k];
        float x1 = sX[(r0 + 1) * DD + k];
        float x2 = sX[(r0 + 2) * DD + k];
        float x3 = sX[(r0 + 3) * DD + k];
        acc0.x += x0 * w.x; acc0.y += x0 * w.y; acc0.z += x0 * w.z; acc0.w += x0 * w.w;
        acc1.x += x1 * w.x; acc1.y += x1 * w.y; acc1.z += x1 * w.z; acc1.w += x1 * w.w;
        acc2.x += x2 * w.x; acc2.y += x2 * w.y; acc2.z += x2 * w.z; acc2.w += x2 * w.w;
        acc3.x += x3 * w.x; acc3.y += x3 * w.y; acc3.z += x3 * w.z; acc3.w += x3 * w.w;
    }

    float4 accs[4] = {acc0, acc1, acc2, acc3};
#pragma unroll
    for (int j = 0; j < 4; j++) {
        int r = base + r0 + j;
        if (r < NN) {
            float s = g_dinv[r];
            g_g[r * 16 + c4] = make_float4(accs[j].x * s, accs[j].y * s,
                                           accs[j].z * s, accs[j].w * s);
        }
    }
}

// ---------------- CSR gather-aggregate (+ finalize fused) ----------------
// 16 threads per node; thread s owns float4 lane s of the 64-dim row.
__global__ __launch_bounds__(256) void k_aggregate(const float* __restrict__ bias,
                                                   float* __restrict__ outext,
                                                   int to_hidden_relu) {
    int gid = blockIdx.x * blockDim.x + threadIdx.x;
    if (gid >= NN16) return;
    int node = gid >> 4;
    int s = gid & 15;

    int beg = __ldg(&g_off[node]);
    int end = __ldg(&g_off[node + 1]);

    float4 a = g_g[node * 16 + s];  // self loop
    float ax = a.x, ay = a.y, az = a.z, aw = a.w;

    int e = beg;
    for (; e + 1 < end; e += 2) {
        int s0 = __ldg(&g_csr_src[e]);
        int s1 = __ldg(&g_csr_src[e + 1]);
        float4 v0 = g_g[s0 * 16 + s];
        float4 v1 = g_g[s1 * 16 + s];
        ax += v0.x + v1.x;
        ay += v0.y + v1.y;
        az += v0.z + v1.z;
        aw += v0.w + v1.w;
    }
    if (e < end) {
        int s0 = __ldg(&g_csr_src[e]);
        float4 v0 = g_g[s0 * 16 + s];
        ax += v0.x; ay += v0.y; az += v0.z; aw += v0.w;
    }

    float sc = g_dinv[node];
    float4 b = ((const float4*)bias)[s];
    float4 o = make_float4(ax * sc + b.x, ay * sc + b.y,
                           az * sc + b.z, aw * sc + b.w);
    if (to_hidden_relu) {
        o.x = fmaxf(o.x, 0.f); o.y = fmaxf(o.y, 0.f);
        o.z = fmaxf(o.z, 0.f); o.w = fmaxf(o.w, 0.f);
        g_hid[gid] = o;
    } else {
        ((float4*)outext)[gid] = o;
    }
}

extern "C" void kernel_launch(void* const* d_in, const int* in_sizes, int n_in,
                              void* d_out, int out_size) {
    const float* x  = (const float*)d_in[0];
    const void*  ei = d_in[1];                  // [2, NE] int32 OR int64
    const float* W1 = (const float*)d_in[2];
    const float* b1 = (const float*)d_in[3];
    const float* W2 = (const float*)d_in[4];
    const float* b2 = (const float*)d_in[5];
    float* out = (float*)d_out;

    // CSR build (once, used by both layers)
    k_detect<<<1, 64>>>(ei);
    k_zero_deg<<<(NN + 255) / 256, 256>>>();
    k_convert_count<<<(NE + 255) / 256, 256>>>(ei);
    k_scan1<<<NBLK, SCAN_B>>>();
    k_scan2<<<1, 256>>>();
    k_scan3<<<NBLK, SCAN_B>>>();
    k_fill<<<(NE + 255) / 256, 256>>>();

    // Layer 1
    k_gemm_scale<<<(NN + 63) / 64, 256>>>(x, W1, 0);
    k_aggregate<<<(NN16 + 255) / 256, 256>>>(b1, nullptr, 1);

    // Layer 2
    k_gemm_scale<<<(NN + 63) / 64, 256>>>(nullptr, W2, 1);
    k_aggregate<<<(NN16 + 255) / 256, 256>>>(b2, out, 0);
}

// round 8
// speedup vs baseline: 4.4933x; 1.0155x over previous
#include <cuda_runtime.h>
#include <cuda_bf16.h>

#define NN 50000
#define NE 800000
#define DD 64
#define NN16 (NN * 16)
#define SCAN_B 256
#define NBLK ((NN + SCAN_B - 1) / SCAN_B)   // 196

// Scratch (static device globals). float4 => 16B aligned.
__device__ float4 g_g[NN * 16];    // g = (X@W) * dinv[row]
__device__ float4 g_hid[NN * 16];  // hidden activation between layers
__device__ float  g_dinv[NN];      // rsqrt(deg+1)
__device__ int    g_src[NE];       // edge sources (int32)
__device__ int    g_dst[NE];       // edge targets (int32)
__device__ int    g_deg[NN];       // in-degree (excl. self loop)
__device__ int    g_off[NN + 1];   // CSR offsets
__device__ int    g_pos[NN];       // fill cursors
__device__ int    g_csr_src[NE];   // sources grouped by dst
__device__ int    g_blk_agg[NBLK]; // lookback: block aggregates
__device__ int    g_blk_flag[NBLK];// lookback: ready flags
__device__ int    g_is64;          // edge dtype flag

// ---------------- prep: dtype detect + zero deg + zero flags ----------------
__global__ __launch_bounds__(SCAN_B) void k_prep(const void* __restrict__ ei) {
    int i = blockIdx.x * SCAN_B + threadIdx.x;
    if (i < NN) g_deg[i] = 0;
    if (i < NBLK) g_blk_flag[i] = 0;
    if (blockIdx.x == 0) {
        // warp-parallel int64 plausibility check on first 64 values
        const long long* p = (const long long*)ei;
        __shared__ int anybad;
        if (threadIdx.x == 0) anybad = 0;
        __syncthreads();
        if (threadIdx.x < 64) {
            long long v = p[threadIdx.x];
            if (v < 0 || v >= NN) atomicOr(&anybad, 1);
        }
        __syncthreads();
        if (threadIdx.x == 0) g_is64 = !anybad;
    }
}

// ---------------- convert to int32 + count in-degrees ----------------
__global__ __launch_bounds__(256) void k_convert_count(const void* __restrict__ ei) {
    int e = blockIdx.x * blockDim.x + threadIdx.x;
    if (e >= NE) return;
    int s, d;
    if (g_is64) {
        const long long* p = (const long long*)ei;
        s = (int)p[e];
        d = (int)p[NE + e];
    } else {
        const int* p = (const int*)ei;
        s = p[e];
        d = p[NE + e];
    }
    s = min(max(s, 0), NN - 1);
    d = min(max(d, 0), NN - 1);
    g_src[e] = s;
    g_dst[e] = d;
    atomicAdd(&g_deg[d], 1);
}

// ---------------- single-kernel decoupled-lookback scan ----------------
// off/pos = exclusive prefix of deg ; dinv = rsqrt(deg+1)
__global__ __launch_bounds__(SCAN_B) void k_scan_lb() {
    __shared__ int sh[SCAN_B];
    __shared__ int prefix;
    int b = blockIdx.x;
    int t = threadIdx.x;
    int i = b * SCAN_B + t;
    int d = (i < NN) ? g_deg[i] : 0;

    // block-local inclusive scan
    sh[t] = d;
    __syncthreads();
#pragma unroll
    for (int o = 1; o < SCAN_B; o <<= 1) {
        int u = (t >= o) ? sh[t - o] : 0;
        __syncthreads();
        sh[t] += u;
        __syncthreads();
    }

    // publish block aggregate
    if (t == 0) {
        g_blk_agg[b] = sh[SCAN_B - 1];
        __threadfence();
        atomicExch(&g_blk_flag[b], 1);
        prefix = 0;
    }
    __syncthreads();

    // warp 0: sum all predecessor aggregates (poll flags through L2)
    if (t < 32) {
        int sum = 0;
        for (int base = 0; base < b; base += 32) {
            int idx = base + t;
            int a = 0;
            if (idx < b) {
                while (atomicAdd(&g_blk_flag[idx], 0) == 0) {}
                a = atomicAdd(&g_blk_agg[idx], 0);  // read through L2
            }
#pragma unroll
            for (int o = 16; o > 0; o >>= 1) a += __shfl_down_sync(0xffffffffu, a, o);
            if (t == 0) sum += a;
        }
        if (t == 0) prefix = sum;
    }
    __syncthreads();

    if (i < NN) {
        int off = prefix + sh[t] - d;   // exclusive
        g_off[i] = off;
        g_pos[i] = off;
        g_dinv[i] = rsqrtf((float)(d + 1));  // +1 self loop
    }
    if (b == 0 && t == 0) g_off[NN] = NE;
}

__global__ __launch_bounds__(256) void k_fill() {
    int e = blockIdx.x * blockDim.x + threadIdx.x;
    if (e >= NE) return;
    int d = g_dst[e];
    int p = atomicAdd(&g_pos[d], 1);
    g_csr_src[p] = g_src[e];
}

// ---------------- GEMM + scale epilogue ----------------
// g = (X @ W) * dinv[row]
__global__ __launch_bounds__(256) void k_gemm_scale(const float* __restrict__ Xext,
                                                    const float* __restrict__ W,
                                                    int use_hidden) {
    __shared__ float sW[DD * DD];   // [k][n]
    __shared__ float sX[64 * DD];   // [r][k]
    const float* X = use_hidden ? (const float*)g_hid : Xext;

    int tid = threadIdx.x;
    int base = blockIdx.x * 64;

    float4* sW4 = (float4*)sW;
    const float4* W4 = (const float4*)W;
#pragma unroll
    for (int i = tid; i < DD * DD / 4; i += 256) sW4[i] = W4[i];

    float4* sX4 = (float4*)sX;
    const float4* X4 = (const float4*)X;
#pragma unroll
    for (int i = tid; i < 64 * DD / 4; i += 256) {
        int r = base + i / (DD / 4);
        sX4[i] = (r < NN) ? X4[(size_t)base * (DD / 4) + i]
                          : make_float4(0.f, 0.f, 0.f, 0.f);
    }
    __syncthreads();

    int c4 = tid & 15;
    int r0 = (tid >> 4) * 4;

    float4 acc0 = make_float4(0, 0, 0, 0), acc1 = acc0, acc2 = acc0, acc3 = acc0;
#pragma unroll
    for (int k = 0; k < DD; k++) {
        float4 w = sW4[k * 16 + c4];
        float x0 = sX[(r0 + 0) * DD + k];
        float x1 = sX[(r0 + 1) * DD + k];
        float x2 = sX[(r0 + 2) * DD + k];
        float x3 = sX[(r0 + 3) * DD + k];
        acc0.x += x0 * w.x; acc0.y += x0 * w.y; acc0.z += x0 * w.z; acc0.w += x0 * w.w;
        acc1.x += x1 * w.x; acc1.y += x1 * w.y; acc1.z += x1 * w.z; acc1.w += x1 * w.w;
        acc2.x += x2 * w.x; acc2.y += x2 * w.y; acc2.z += x2 * w.z; acc2.w += x2 * w.w;
        acc3.x += x3 * w.x; acc3.y += x3 * w.y; acc3.z += x3 * w.z; acc3.w += x3 * w.w;
    }

    float4 accs[4] = {acc0, acc1, acc2, acc3};
#pragma unroll
    for (int j = 0; j < 4; j++) {
        int r = base + r0 + j;
        if (r < NN) {
            float s = g_dinv[r];
            g_g[r * 16 + c4] = make_float4(accs[j].x * s, accs[j].y * s,
                                           accs[j].z * s, accs[j].w * s);
        }
    }
}

// ---------------- CSR gather-aggregate (+ finalize fused) ----------------
// 16 threads per node; thread s owns float4 lane s of the 64-dim row.
// Unroll 4: four independent gathers in flight per thread.
__global__ __launch_bounds__(256) void k_aggregate(const float* __restrict__ bias,
                                                   float* __restrict__ outext,
                                                   int to_hidden_relu) {
    int gid = blockIdx.x * blockDim.x + threadIdx.x;
    if (gid >= NN16) return;
    int node = gid >> 4;
    int s = gid & 15;

    int beg = __ldg(&g_off[node]);
    int end = __ldg(&g_off[node + 1]);

    float4 a = g_g[node * 16 + s];  // self loop
    float ax = a.x, ay = a.y, az = a.z, aw = a.w;

    int e = beg;
    for (; e + 3 < end; e += 4) {
        int s0 = __ldg(&g_csr_src[e]);
        int s1 = __ldg(&g_csr_src[e + 1]);
        int s2 = __ldg(&g_csr_src[e + 2]);
        int s3 = __ldg(&g_csr_src[e + 3]);
        float4 v0 = g_g[s0 * 16 + s];
        float4 v1 = g_g[s1 * 16 + s];
        float4 v2 = g_g[s2 * 16 + s];
        float4 v3 = g_g[s3 * 16 + s];
        ax += (v0.x + v1.x) + (v2.x + v3.x);
        ay += (v0.y + v1.y) + (v2.y + v3.y);
        az += (v0.z + v1.z) + (v2.z + v3.z);
        aw += (v0.w + v1.w) + (v2.w + v3.w);
    }
    for (; e < end; e++) {
        int s0 = __ldg(&g_csr_src[e]);
        float4 v0 = g_g[s0 * 16 + s];
        ax += v0.x; ay += v0.y; az += v0.z; aw += v0.w;
    }

    float sc = g_dinv[node];
    float4 b = ((const float4*)bias)[s];
    float4 o = make_float4(ax * sc + b.x, ay * sc + b.y,
                           az * sc + b.z, aw * sc + b.w);
    if (to_hidden_relu) {
        o.x = fmaxf(o.x, 0.f); o.y = fmaxf(o.y, 0.f);
        o.z = fmaxf(o.z, 0.f); o.w = fmaxf(o.w, 0.f);
        g_hid[gid] = o;
    } else {
        ((float4*)outext)[gid] = o;
    }
}

extern "C" void kernel_launch(void* const* d_in, const int* in_sizes, int n_in,
                              void* d_out, int out_size) {
    const float* x  = (const float*)d_in[0];
    const void*  ei = d_in[1];                  // [2, NE] int32 OR int64
    const float* W1 = (const float*)d_in[2];
    const float* b1 = (const float*)d_in[3];
    const float* W2 = (const float*)d_in[4];
    const float* b2 = (const float*)d_in[5];
    float* out = (float*)d_out;

    // CSR build (once, used by both layers)
    k_prep<<<NBLK, SCAN_B>>>(ei);
    k_convert_count<<<(NE + 255) / 256, 256>>>(ei);
    k_scan_lb<<<NBLK, SCAN_B>>>();
    k_fill<<<(NE + 255) / 256, 256>>>();

    // Layer 1
    k_gemm_scale<<<(NN + 63) / 64, 256>>>(x, W1, 0);
    k_aggregate<<<(NN16 + 255) / 256, 256>>>(b1, nullptr, 1);

    // Layer 2
    k_gemm_scale<<<(NN + 63) / 64, 256>>>(nullptr, W2, 1);
    k_aggregate<<<(NN16 + 255) / 256, 256>>>(b2, out, 0);
}